// round 2
// baseline (speedup 1.0000x reference)
#include <cuda_runtime.h>

// Problem: out[b,l,e] = (1/(l+1)) * sum_{i<=l} (x[b,i,:] @ W[e,:])
// B=4, L=8192, D=512.  x: [4,8192,512] f32, W: [512,512] f32, out f32.

#define M_TOT 32768   // B*L
#define N_TOT 512
#define K_TOT 512
#define LSEQ  8192
#define BM 128
#define BN 64
#define BK 16
#define NCHUNK 64     // LSEQ / BM

// Scratch (device globals: allocation-guard-safe).
__device__ float g_V[(size_t)M_TOT * N_TOT];        // 64 MB: V = x @ W^T
__device__ float g_S[4 * NCHUNK * N_TOT];           // per-chunk column sums

// ---------------- packed f32x2 helpers (sm_100+) ----------------
__device__ __forceinline__ unsigned long long dup2(float x) {
    unsigned long long r;
    asm("mov.b64 %0, {%1, %1};" : "=l"(r) : "f"(x));
    return r;
}
__device__ __forceinline__ void fma2(unsigned long long& d,
                                     unsigned long long a,
                                     unsigned long long b) {
    asm("fma.rn.f32x2 %0, %1, %2, %0;" : "+l"(d) : "l"(a), "l"(b));
}
__device__ __forceinline__ void unpack2(unsigned long long v, float& lo, float& hi) {
    asm("mov.b64 {%0, %1}, %2;" : "=f"(lo), "=f"(hi) : "l"(v));
}

// ---------------- GEMM: V = X @ W^T, fused chunk-sum epilogue ----------------
// Tile: 128x64, BK=16, 256 threads, per-thread 8(M)x4(N) as 4 f32x2-pairs x 4.
__global__ __launch_bounds__(256) void gemm_kernel(const float* __restrict__ X,
                                                   const float* __restrict__ W) {
    __shared__ float As[BK][BM];   // K-major (transposed) for broadcast reads
    __shared__ float Bs[BK][BN];
    __shared__ float red[16][BN];  // cross-thread column-sum reduction

    const int tid = threadIdx.x;
    const int tx = tid & 15;        // N split: 16 threads * 4 cols
    const int ty = tid >> 4;        // M split: 16 threads * 8 rows
    const int n0 = blockIdx.x * BN;
    const int m0 = blockIdx.y * BM;

    // Global-load assignments
    const int arow = tid >> 1;            // 0..127
    const int acg  = (tid & 1) * 8;       // 0 or 8 (k-offset)
    const int brow = tid >> 2;            // 0..63
    const int bcg  = (tid & 3) * 4;       // 0,4,8,12 (k-offset)

    const float* Aptr = X + (size_t)(m0 + arow) * K_TOT + acg;
    const float* Bptr = W + (size_t)(n0 + brow) * K_TOT + bcg;

    unsigned long long acc[4][4];
#pragma unroll
    for (int i = 0; i < 4; i++)
#pragma unroll
        for (int j = 0; j < 4; j++) acc[i][j] = 0ULL;

    // Preload tile 0
    float4 a0 = *(const float4*)(Aptr);
    float4 a1 = *(const float4*)(Aptr + 4);
    float4 bb = *(const float4*)(Bptr);

    As[acg + 0][arow] = a0.x; As[acg + 1][arow] = a0.y;
    As[acg + 2][arow] = a0.z; As[acg + 3][arow] = a0.w;
    As[acg + 4][arow] = a1.x; As[acg + 5][arow] = a1.y;
    As[acg + 6][arow] = a1.z; As[acg + 7][arow] = a1.w;
    Bs[bcg + 0][brow] = bb.x; Bs[bcg + 1][brow] = bb.y;
    Bs[bcg + 2][brow] = bb.z; Bs[bcg + 3][brow] = bb.w;
    __syncthreads();

    const int KT = K_TOT / BK;  // 32
    for (int kt = 0; kt < KT; kt++) {
        // Prefetch next tile into registers while computing current
        if (kt + 1 < KT) {
            const float* Ap = Aptr + (kt + 1) * BK;
            a0 = *(const float4*)(Ap);
            a1 = *(const float4*)(Ap + 4);
            bb = *(const float4*)(Bptr + (kt + 1) * BK);
        }
#pragma unroll
        for (int k = 0; k < BK; k++) {
            // A: 2 broadcast 16B LDS per warp; B: 16 distinct 16B LDS.
            ulonglong2 av0 = *(const ulonglong2*)&As[k][ty * 8];
            ulonglong2 av1 = *(const ulonglong2*)&As[k][ty * 8 + 4];
            float4 bf = *(const float4*)&Bs[k][tx * 4];
            // Hoist broadcast packs so the 16 fma.f32x2 issue back-to-back.
            unsigned long long b0 = dup2(bf.x), b1 = dup2(bf.y),
                               b2 = dup2(bf.z), b3 = dup2(bf.w);
            unsigned long long a2[4] = {av0.x, av0.y, av1.x, av1.y};
#pragma unroll
            for (int i = 0; i < 4; i++) {
                fma2(acc[i][0], a2[i], b0);
                fma2(acc[i][1], a2[i], b1);
                fma2(acc[i][2], a2[i], b2);
                fma2(acc[i][3], a2[i], b3);
            }
        }
        __syncthreads();
        if (kt + 1 < KT) {
            As[acg + 0][arow] = a0.x; As[acg + 1][arow] = a0.y;
            As[acg + 2][arow] = a0.z; As[acg + 3][arow] = a0.w;
            As[acg + 4][arow] = a1.x; As[acg + 5][arow] = a1.y;
            As[acg + 6][arow] = a1.z; As[acg + 7][arow] = a1.w;
            Bs[bcg + 0][brow] = bb.x; Bs[bcg + 1][brow] = bb.y;
            Bs[bcg + 2][brow] = bb.z; Bs[bcg + 3][brow] = bb.w;
            __syncthreads();
        }
    }

    // Epilogue: store V tile + reduce 128-row chunk column sums
    float colsum[4] = {0.f, 0.f, 0.f, 0.f};
#pragma unroll
    for (int i = 0; i < 4; i++) {
        float lo[4], hi[4];
#pragma unroll
        for (int j = 0; j < 4; j++) {
            unpack2(acc[i][j], lo[j], hi[j]);
            colsum[j] += lo[j] + hi[j];
        }
        const int r0 = m0 + ty * 8 + 2 * i;
        float4 v0 = make_float4(lo[0], lo[1], lo[2], lo[3]);
        float4 v1 = make_float4(hi[0], hi[1], hi[2], hi[3]);
        *(float4*)&g_V[(size_t)r0 * N_TOT + n0 + tx * 4] = v0;
        *(float4*)&g_V[(size_t)(r0 + 1) * N_TOT + n0 + tx * 4] = v1;
    }
#pragma unroll
    for (int j = 0; j < 4; j++) red[ty][tx * 4 + j] = colsum[j];
    __syncthreads();
    if (tid < 64) {
        float s = 0.f;
#pragma unroll
        for (int t = 0; t < 16; t++) s += red[t][tid];
        const int b = m0 / LSEQ;
        const int c = (m0 % LSEQ) / BM;   // chunk index (BM == chunk size)
        g_S[(b * NCHUNK + c) * N_TOT + n0 + tid] = s;
    }
}

// ---------------- Scan: running mean from V + chunk sums ----------------
// block = (b, chunk); thread owns 4 columns (float4) over the 128-row chunk.
__global__ __launch_bounds__(128) void scan_kernel(float* __restrict__ out) {
    const int b = blockIdx.x;
    const int c = blockIdx.y;
    const int d4 = threadIdx.x;   // 0..127 -> columns [4*d4, 4*d4+4)

    // Exclusive prefix of chunk sums (coalesced; g_S = 512 KB, L2-resident)
    float4 off = make_float4(0.f, 0.f, 0.f, 0.f);
    for (int cc = 0; cc < c; cc++) {
        float4 s = *(const float4*)&g_S[(b * NCHUNK + cc) * N_TOT + d4 * 4];
        off.x += s.x; off.y += s.y; off.z += s.z; off.w += s.w;
    }

    const int l0 = c * BM;
    const size_t base = ((size_t)b * LSEQ + l0) * N_TOT + d4 * 4;
    float4 run = off;
#pragma unroll 4
    for (int i = 0; i < BM; i++) {
        float4 v = *(const float4*)&g_V[base + (size_t)i * N_TOT];
        run.x += v.x; run.y += v.y; run.z += v.z; run.w += v.w;
        const float inv = 1.0f / (float)(l0 + i + 1);
        float4 o = make_float4(run.x * inv, run.y * inv, run.z * inv, run.w * inv);
        *(float4*)&out[base + (size_t)i * N_TOT] = o;
    }
}

// ---------------- launch ----------------
extern "C" void kernel_launch(void* const* d_in, const int* in_sizes, int n_in,
                              void* d_out, int out_size) {
    const float* x = (const float*)d_in[0];   // [4,8192,512] f32
    const float* W = (const float*)d_in[1];   // [512,512] f32
    float* out = (float*)d_out;               // [4,8192,512] f32

    dim3 g1(N_TOT / BN, M_TOT / BM);          // (8, 256)
    gemm_kernel<<<g1, 256>>>(x, W);

    dim3 g2(4, NCHUNK);                       // (4, 64)
    scan_kernel<<<g2, 128>>>(out);
}

// round 5
// speedup vs baseline: 2.3941x; 2.3941x over previous
#include <cuda_runtime.h>
#include <cuda_bf16.h>
#include <cstdint>

// out[b,l,e] = (1/(l+1)) * sum_{i<=l} (x[b,i,:] @ W[e,:]);  B=4, L=8192, D=512.
// tcgen05 unavailable (harness emits .target sm_100, not sm_100a) -> base-PTX
// mma.sync bf16 (HMMA) with split hi/lo for fp32-grade accuracy.
// Pipeline: convert(x,W -> bf16 hi/lo) -> mma.sync GEMM (V + 32-row chunk sums)
//           -> parallel prefix(S) -> scan(V,S -> out)

#define M_TOT 32768
#define NTOT  512
#define KTOT  512
#define LSEQ  8192
#define BM    128
#define BN    128
#define BK    64
#define NKC   (KTOT / BK)     // 8 stages
#define CHUNK 32
#define NCHK  (LSEQ / CHUNK)  // 256 chunks per batch

// -------- scratch (device globals: allocation-guard-safe) --------
__device__ __nv_bfloat16 g_Xhi[(size_t)M_TOT * KTOT];
__device__ __nv_bfloat16 g_Xlo[(size_t)M_TOT * KTOT];
__device__ __nv_bfloat16 g_Whi[NTOT * KTOT];
__device__ __nv_bfloat16 g_Wlo[NTOT * KTOT];
__device__ float g_V[(size_t)M_TOT * NTOT];          // 64 MB
__device__ float g_S[4 * (size_t)NTOT * NCHK];       // 2 MB, layout [b][d][c]

// -------- helpers --------
__device__ __forceinline__ uint32_t smem_u32(const void* p) {
    uint32_t a;
    asm("{ .reg .u64 t; cvta.to.shared.u64 t, %1; cvt.u32.u64 %0, t; }" : "=r"(a) : "l"(p));
    return a;
}
#define SWZ128(o) ((o) ^ (((o) >> 3) & 0x70))

__device__ __forceinline__ void cp16(uint32_t dst, const void* src) {
    asm volatile("cp.async.cg.shared.global [%0], [%1], 16;" :: "r"(dst), "l"(src));
}
__device__ __forceinline__ void cp_commit() { asm volatile("cp.async.commit_group;" ::: "memory"); }
template <int N> __device__ __forceinline__ void cp_wait() {
    asm volatile("cp.async.wait_group %0;" :: "n"(N) : "memory");
}

__device__ __forceinline__ void ldm_x4(uint32_t* r, uint32_t a) {
    asm volatile("ldmatrix.sync.aligned.m8n8.x4.shared.b16 {%0,%1,%2,%3}, [%4];"
                 : "=r"(r[0]), "=r"(r[1]), "=r"(r[2]), "=r"(r[3]) : "r"(a));
}
__device__ __forceinline__ void ldm_x2(uint32_t* r, uint32_t a) {
    asm volatile("ldmatrix.sync.aligned.m8n8.x2.shared.b16 {%0,%1}, [%2];"
                 : "=r"(r[0]), "=r"(r[1]) : "r"(a));
}
__device__ __forceinline__ void mma16816(float* d, const uint32_t* a, const uint32_t* b) {
    asm volatile("mma.sync.aligned.m16n8k16.row.col.f32.bf16.bf16.f32 "
                 "{%0,%1,%2,%3}, {%4,%5,%6,%7}, {%8,%9}, {%0,%1,%2,%3};"
                 : "+f"(d[0]), "+f"(d[1]), "+f"(d[2]), "+f"(d[3])
                 : "r"(a[0]), "r"(a[1]), "r"(a[2]), "r"(a[3]), "r"(b[0]), "r"(b[1]));
}

// SMEM stage layout (bytes): Ahi[128x64 bf16]=16K, Alo=16K, Bhi[128x64]=16K, Blo=16K
#define OFF_AHI 0
#define OFF_ALO 16384
#define OFF_BHI 32768
#define OFF_BLO 49152
#define STAGE_BYTES 65536
#define SMEM_DYN (2 * STAGE_BYTES + 1024)
#define VS_STRIDE 132                 // f32 words per Vs row (pad vs 128)
#define OFF_PART 98304                // partial chunk sums [8][128] f32

// ================= convert: f32 -> bf16 hi/lo =================
__global__ __launch_bounds__(256) void convert_kernel(const float* __restrict__ x,
                                                      const float* __restrict__ w) {
    const size_t nx4 = ((size_t)M_TOT * KTOT) / 4;
    const size_t nw4 = ((size_t)NTOT * KTOT) / 4;
    const size_t tot = nx4 + nw4;
    for (size_t i = (size_t)blockIdx.x * blockDim.x + threadIdx.x; i < tot;
         i += (size_t)gridDim.x * blockDim.x) {
        const bool isx = i < nx4;
        const size_t j = isx ? i : i - nx4;
        float4 v = isx ? ((const float4*)x)[j] : ((const float4*)w)[j];
        float f[4] = {v.x, v.y, v.z, v.w};
        uint32_t hp[2], lp[2];
#pragma unroll
        for (int g = 0; g < 2; g++) {
            __nv_bfloat16 h0 = __float2bfloat16_rn(f[2 * g]);
            __nv_bfloat16 h1 = __float2bfloat16_rn(f[2 * g + 1]);
            __nv_bfloat16 l0 = __float2bfloat16_rn(f[2 * g] - __bfloat162float(h0));
            __nv_bfloat16 l1 = __float2bfloat16_rn(f[2 * g + 1] - __bfloat162float(h1));
            hp[g] = (uint32_t)__bfloat16_as_ushort(h0) | ((uint32_t)__bfloat16_as_ushort(h1) << 16);
            lp[g] = (uint32_t)__bfloat16_as_ushort(l0) | ((uint32_t)__bfloat16_as_ushort(l1) << 16);
        }
        uint2 hv = make_uint2(hp[0], hp[1]), lv = make_uint2(lp[0], lp[1]);
        if (isx) { ((uint2*)g_Xhi)[j] = hv; ((uint2*)g_Xlo)[j] = lv; }
        else     { ((uint2*)g_Whi)[j] = hv; ((uint2*)g_Wlo)[j] = lv; }
    }
}

// ================= GEMM: V = X @ W^T via split-bf16 mma.sync =================
extern __shared__ char dynsmem[];

__device__ __forceinline__ void load_stage(uint32_t sb, int buf, int kc, int m0, int n0, int tid) {
    const uint32_t st = sb + buf * STAGE_BYTES;
    const int kbase = kc * BK;
    const __nv_bfloat16* srcs[4] = {g_Xhi, g_Xlo, g_Whi, g_Wlo};
    const uint32_t offs[4] = {OFF_AHI, OFF_ALO, OFF_BHI, OFF_BLO};
    const int rows0[4] = {1, 1, 0, 0};  // 1 -> row uses m0, 0 -> n0
#pragma unroll
    for (int a = 0; a < 4; a++) {
        const __nv_bfloat16* src = srcs[a];
        const uint32_t base = st + offs[a];
        const int r0 = rows0[a] ? m0 : n0;
#pragma unroll
        for (int i = 0; i < 4; i++) {
            int u = tid + i * 256;          // 0..1023
            int r = u >> 3, c8 = u & 7;     // row 0..127, 16B chunk 0..7
            uint32_t off = (uint32_t)(r * 128 + c8 * 16);
            cp16(base + SWZ128(off), src + (size_t)(r0 + r) * KTOT + kbase + c8 * 8);
        }
    }
}

__global__ __launch_bounds__(256, 1) void gemm_kernel() {
    const int tid = threadIdx.x;
    const int wid = tid >> 5;
    const int lane = tid & 31;
    const int n0 = blockIdx.x * BN;
    const int m0 = blockIdx.y * BM;
    const int wm = wid & 1;            // m half (64 rows)
    const int wn = wid >> 1;           // n quarter (32 cols)

    uint32_t sb = (smem_u32(dynsmem) + 1023u) & ~1023u;

    float d[4][4][4];
#pragma unroll
    for (int mi = 0; mi < 4; mi++)
#pragma unroll
        for (int ni = 0; ni < 4; ni++)
#pragma unroll
            for (int j = 0; j < 4; j++) d[mi][ni][j] = 0.f;

    // per-lane ldmatrix address components.
    // Swizzle XOR term (row&7)*16 == (lane&7)*16 for every participating lane
    // because all row bases (wm*64, mi*16, wn*32, ni*8) are multiples of 8.
    const int l7x16 = (lane & 7) * 16;
    const int aRow = wm * 64 + (lane & 15);            // + mi*16
    const int kHalfA = ((lane >> 4) & 1) * 16;         // bytes (+8 bf16)
    const int bRowN = (lane & 7);                      // + wn*32 + ni*8
    const int kHalfB = ((lane >> 3) & 1) * 16;

    load_stage(sb, 0, 0, m0, n0, tid);
    cp_commit();

    for (int kc = 0; kc < NKC; kc++) {
        if (kc + 1 < NKC) {
            load_stage(sb, (kc + 1) & 1, kc + 1, m0, n0, tid);
            cp_commit();
            cp_wait<1>();
        } else {
            cp_wait<0>();
        }
        __syncthreads();

        const uint32_t st = sb + (kc & 1) * STAGE_BYTES;
#pragma unroll
        for (int ks = 0; ks < 4; ks++) {
            const uint32_t colA = (uint32_t)((ks * 32 + kHalfA) ^ l7x16);
            const uint32_t colB = (uint32_t)((ks * 32 + kHalfB) ^ l7x16);
            uint32_t ahi[4][4], alo[4][4], bhi[4][2], blo[4][2];
#pragma unroll
            for (int mi = 0; mi < 4; mi++) {
                const uint32_t ra = (uint32_t)((aRow + mi * 16) * 128) + colA;
                ldm_x4(ahi[mi], st + OFF_AHI + ra);
                ldm_x4(alo[mi], st + OFF_ALO + ra);
            }
#pragma unroll
            for (int ni = 0; ni < 4; ni++) {
                const uint32_t rb = (uint32_t)((wn * 32 + ni * 8 + bRowN) * 128) + colB;
                ldm_x2(bhi[ni], st + OFF_BHI + rb);
                ldm_x2(blo[ni], st + OFF_BLO + rb);
            }
#pragma unroll
            for (int mi = 0; mi < 4; mi++)
#pragma unroll
                for (int ni = 0; ni < 4; ni++) {
                    mma16816(d[mi][ni], ahi[mi], bhi[ni]);
                    mma16816(d[mi][ni], ahi[mi], blo[ni]);
                    mma16816(d[mi][ni], alo[mi], bhi[ni]);
                }
        }
        __syncthreads();
    }

    // ---- epilogue: stage D tile in smem, coalesced V store + chunk sums ----
    {
        const int g = lane >> 2, tig = lane & 3;
        float* vs = (float*)dynsmem;   // reuse stage buffers: 128 x VS_STRIDE f32
#pragma unroll
        for (int mi = 0; mi < 4; mi++)
#pragma unroll
            for (int ni = 0; ni < 4; ni++) {
                const int r0 = wm * 64 + mi * 16 + g;
                const int c  = wn * 32 + ni * 8 + 2 * tig;
                *(float2*)&vs[(size_t)r0 * VS_STRIDE + c] =
                    make_float2(d[mi][ni][0], d[mi][ni][1]);
                *(float2*)&vs[(size_t)(r0 + 8) * VS_STRIDE + c] =
                    make_float2(d[mi][ni][2], d[mi][ni][3]);
            }
    }
    __syncthreads();

    // writeout: warp w -> rows w*16..w*16+15; lane -> 4 cols (coalesced float4)
    {
        float* vs = (float*)dynsmem;
        float* part = (float*)(dynsmem + OFF_PART);  // [8][128]
        float4 sum = make_float4(0.f, 0.f, 0.f, 0.f);
#pragma unroll
        for (int i = 0; i < 16; i++) {
            const int r = wid * 16 + i;
            float4 v = *(float4*)&vs[(size_t)r * VS_STRIDE + lane * 4];
            sum.x += v.x; sum.y += v.y; sum.z += v.z; sum.w += v.w;
            *(float4*)&g_V[(size_t)(m0 + r) * NTOT + n0 + lane * 4] = v;
        }
        *(float4*)&part[wid * 128 + lane * 4] = sum;
    }
    __syncthreads();

    // chunk sums: chunk c (32 rows) = warps 2c,2c+1; g_S layout [b][d][c]
    {
        const float* part = (const float*)(dynsmem + OFF_PART);
        const int b = m0 >> 13;                // /8192
        const int cBase = (m0 & 8191) >> 5;    // /32
#pragma unroll
        for (int it = 0; it < 2; it++) {
            const int idx = tid + it * 256;    // 0..511
            const int c = idx >> 7, col = idx & 127;
            const float val = part[(2 * c) * 128 + col] + part[(2 * c + 1) * 128 + col];
            g_S[((size_t)(b * NTOT + n0 + col)) * NCHK + cBase + c] = val;
        }
    }
}

// ================= exclusive prefix over chunk sums (per b,d) =================
__global__ __launch_bounds__(256) void prefix_kernel() {
    __shared__ float wsum[8];
    const size_t base = (size_t)blockIdx.x * NCHK;   // blockIdx.x = b*512 + d
    const int tid = threadIdx.x, lane = tid & 31, wid = tid >> 5;
    const float v = g_S[base + tid];
    float inc = v;
#pragma unroll
    for (int o = 1; o < 32; o <<= 1) {
        float t = __shfl_up_sync(0xffffffffu, inc, o);
        if (lane >= o) inc += t;
    }
    if (lane == 31) wsum[wid] = inc;
    __syncthreads();
    if (tid == 0) {
        float run = 0.f;
#pragma unroll
        for (int w = 0; w < 8; w++) { float t = wsum[w]; wsum[w] = run; run += t; }
    }
    __syncthreads();
    g_S[base + tid] = inc - v + wsum[wid];   // exclusive prefix
}

// ================= scan: running mean over 32-row chunks =================
__global__ __launch_bounds__(128) void scan_kernel(float* __restrict__ out) {
    const int c = blockIdx.x;
    const int b = blockIdx.y;
    const int d4 = threadIdx.x;                     // cols [4*d4, 4*d4+4)
    float4 run;
    run.x = g_S[((size_t)(b * NTOT + d4 * 4 + 0)) * NCHK + c];
    run.y = g_S[((size_t)(b * NTOT + d4 * 4 + 1)) * NCHK + c];
    run.z = g_S[((size_t)(b * NTOT + d4 * 4 + 2)) * NCHK + c];
    run.w = g_S[((size_t)(b * NTOT + d4 * 4 + 3)) * NCHK + c];
    const int l0 = c * CHUNK;
    const size_t base = ((size_t)b * LSEQ + l0) * NTOT + d4 * 4;
#pragma unroll 8
    for (int i = 0; i < CHUNK; i++) {
        float4 v = *(const float4*)&g_V[base + (size_t)i * NTOT];
        run.x += v.x; run.y += v.y; run.z += v.z; run.w += v.w;
        const float inv = 1.0f / (float)(l0 + i + 1);
        *(float4*)&out[base + (size_t)i * NTOT] =
            make_float4(run.x * inv, run.y * inv, run.z * inv, run.w * inv);
    }
}

// ================= launch =================
extern "C" void kernel_launch(void* const* d_in, const int* in_sizes, int n_in,
                              void* d_out, int out_size) {
    const float* x = (const float*)d_in[0];
    const float* W = (const float*)d_in[1];
    float* out = (float*)d_out;

    convert_kernel<<<2048, 256>>>(x, W);

    cudaFuncSetAttribute(gemm_kernel, cudaFuncAttributeMaxDynamicSharedMemorySize, SMEM_DYN);
    gemm_kernel<<<dim3(NTOT / BN, M_TOT / BM), 256, SMEM_DYN>>>();  // (4, 256)

    prefix_kernel<<<4 * NTOT, 256>>>();                              // 2048 blocks
    scan_kernel<<<dim3(NCHK, 4), 128>>>(out);
}

// round 8
// speedup vs baseline: 2.4185x; 1.0102x over previous
#include <cuda_runtime.h>
#include <cuda_bf16.h>
#include <cstdint>

// out[b,l,e] = (1/(l+1)) * sum_{i<=l} (x[b,i,:] @ W[e,:]);  B=4, L=8192, D=512.
// tcgen05 unavailable (harness emits .target sm_100, not sm_100a) -> base-PTX
// mma.sync bf16 (HMMA) with split hi/lo for fp32-grade accuracy.
// Pipeline: convert(x,W -> bf16 hi/lo) -> mma.sync GEMM, 3-stage cp.async
//           (V + 16-row chunk sums) -> parallel prefix(S) -> scan(V,S -> out)

#define M_TOT 32768
#define NTOT  512
#define KTOT  512
#define LSEQ  8192
#define BM    128
#define BN    128
#define BK    64
#define NKC   (KTOT / BK)     // 8 stages
#define CHUNK 16
#define NCHK  (LSEQ / CHUNK)  // 512 chunks per batch

// -------- scratch (device globals: allocation-guard-safe) --------
__device__ __nv_bfloat16 g_Xhi[(size_t)M_TOT * KTOT];
__device__ __nv_bfloat16 g_Xlo[(size_t)M_TOT * KTOT];
__device__ __nv_bfloat16 g_Whi[NTOT * KTOT];
__device__ __nv_bfloat16 g_Wlo[NTOT * KTOT];
__device__ float g_V[(size_t)M_TOT * NTOT];          // 64 MB
__device__ float g_S[4 * (size_t)NTOT * NCHK];       // 4 MB, layout [b][d][c]

// -------- helpers --------
__device__ __forceinline__ uint32_t smem_u32(const void* p) {
    uint32_t a;
    asm("{ .reg .u64 t; cvta.to.shared.u64 t, %1; cvt.u32.u64 %0, t; }" : "=r"(a) : "l"(p));
    return a;
}
#define SWZ128(o) ((o) ^ (((o) >> 3) & 0x70))

__device__ __forceinline__ void cp16(uint32_t dst, const void* src) {
    asm volatile("cp.async.cg.shared.global [%0], [%1], 16;" :: "r"(dst), "l"(src));
}
__device__ __forceinline__ void cp_commit() { asm volatile("cp.async.commit_group;" ::: "memory"); }
template <int N> __device__ __forceinline__ void cp_wait() {
    asm volatile("cp.async.wait_group %0;" :: "n"(N) : "memory");
}

__device__ __forceinline__ void ldm_x4(uint32_t* r, uint32_t a) {
    asm volatile("ldmatrix.sync.aligned.m8n8.x4.shared.b16 {%0,%1,%2,%3}, [%4];"
                 : "=r"(r[0]), "=r"(r[1]), "=r"(r[2]), "=r"(r[3]) : "r"(a));
}
__device__ __forceinline__ void ldm_x2(uint32_t* r, uint32_t a) {
    asm volatile("ldmatrix.sync.aligned.m8n8.x2.shared.b16 {%0,%1}, [%2];"
                 : "=r"(r[0]), "=r"(r[1]) : "r"(a));
}
__device__ __forceinline__ void mma16816(float* d, const uint32_t* a, const uint32_t* b) {
    asm volatile("mma.sync.aligned.m16n8k16.row.col.f32.bf16.bf16.f32 "
                 "{%0,%1,%2,%3}, {%4,%5,%6,%7}, {%8,%9}, {%0,%1,%2,%3};"
                 : "+f"(d[0]), "+f"(d[1]), "+f"(d[2]), "+f"(d[3])
                 : "r"(a[0]), "r"(a[1]), "r"(a[2]), "r"(a[3]), "r"(b[0]), "r"(b[1]));
}

// SMEM stage layout (bytes): Ahi[128x64 bf16]=16K, Alo=16K, Bhi[128x64]=16K, Blo=16K
#define OFF_AHI 0
#define OFF_ALO 16384
#define OFF_BHI 32768
#define OFF_BLO 49152
#define STAGE_BYTES 65536
#define NSTAGE 3
#define SMEM_DYN (NSTAGE * STAGE_BYTES + 1024)
#define VS_STRIDE 132                 // f32 words per Vs row (pad vs 128)
#define OFF_PART 98304                // partial chunk sums [8][128] f32

// ================= convert: f32 -> bf16 hi/lo =================
__global__ __launch_bounds__(256) void convert_kernel(const float* __restrict__ x,
                                                      const float* __restrict__ w) {
    const size_t nx4 = ((size_t)M_TOT * KTOT) / 4;
    const size_t nw4 = ((size_t)NTOT * KTOT) / 4;
    const size_t tot = nx4 + nw4;
    for (size_t i = (size_t)blockIdx.x * blockDim.x + threadIdx.x; i < tot;
         i += (size_t)gridDim.x * blockDim.x) {
        const bool isx = i < nx4;
        const size_t j = isx ? i : i - nx4;
        float4 v = isx ? ((const float4*)x)[j] : ((const float4*)w)[j];
        float f[4] = {v.x, v.y, v.z, v.w};
        uint32_t hp[2], lp[2];
#pragma unroll
        for (int g = 0; g < 2; g++) {
            __nv_bfloat16 h0 = __float2bfloat16_rn(f[2 * g]);
            __nv_bfloat16 h1 = __float2bfloat16_rn(f[2 * g + 1]);
            __nv_bfloat16 l0 = __float2bfloat16_rn(f[2 * g] - __bfloat162float(h0));
            __nv_bfloat16 l1 = __float2bfloat16_rn(f[2 * g + 1] - __bfloat162float(h1));
            hp[g] = (uint32_t)__bfloat16_as_ushort(h0) | ((uint32_t)__bfloat16_as_ushort(h1) << 16);
            lp[g] = (uint32_t)__bfloat16_as_ushort(l0) | ((uint32_t)__bfloat16_as_ushort(l1) << 16);
        }
        uint2 hv = make_uint2(hp[0], hp[1]), lv = make_uint2(lp[0], lp[1]);
        if (isx) { ((uint2*)g_Xhi)[j] = hv; ((uint2*)g_Xlo)[j] = lv; }
        else     { ((uint2*)g_Whi)[j] = hv; ((uint2*)g_Wlo)[j] = lv; }
    }
}

// ================= GEMM: V = X @ W^T via split-bf16 mma.sync =================
extern __shared__ char dynsmem[];

__device__ __forceinline__ void load_stage(uint32_t sb, int buf, int kc, int m0, int n0, int tid) {
    const uint32_t st = sb + buf * STAGE_BYTES;
    const int kbase = kc * BK;
    const __nv_bfloat16* srcs[4] = {g_Xhi, g_Xlo, g_Whi, g_Wlo};
    const uint32_t offs[4] = {OFF_AHI, OFF_ALO, OFF_BHI, OFF_BLO};
    const int rows0[4] = {1, 1, 0, 0};  // 1 -> row uses m0, 0 -> n0
#pragma unroll
    for (int a = 0; a < 4; a++) {
        const __nv_bfloat16* src = srcs[a];
        const uint32_t base = st + offs[a];
        const int r0 = rows0[a] ? m0 : n0;
#pragma unroll
        for (int i = 0; i < 4; i++) {
            int u = tid + i * 256;          // 0..1023
            int r = u >> 3, c8 = u & 7;     // row 0..127, 16B chunk 0..7
            uint32_t off = (uint32_t)(r * 128 + c8 * 16);
            cp16(base + SWZ128(off), src + (size_t)(r0 + r) * KTOT + kbase + c8 * 8);
        }
    }
}

__global__ __launch_bounds__(256, 1) void gemm_kernel() {
    const int tid = threadIdx.x;
    const int wid = tid >> 5;
    const int lane = tid & 31;
    const int n0 = blockIdx.x * BN;
    const int m0 = blockIdx.y * BM;
    const int wm = wid & 1;            // m half (64 rows)
    const int wn = wid >> 1;           // n quarter (32 cols)

    uint32_t sb = (smem_u32(dynsmem) + 1023u) & ~1023u;

    float d[4][4][4];
#pragma unroll
    for (int mi = 0; mi < 4; mi++)
#pragma unroll
        for (int ni = 0; ni < 4; ni++)
#pragma unroll
            for (int j = 0; j < 4; j++) d[mi][ni][j] = 0.f;

    // per-lane ldmatrix address components.
    // Swizzle XOR term (row&7)*16 == (lane&7)*16 for every participating lane
    // because all row bases (wm*64, mi*16, wn*32, ni*8) are multiples of 8.
    const int l7x16 = (lane & 7) * 16;
    const int aRow = wm * 64 + (lane & 15);            // + mi*16
    const int kHalfA = ((lane >> 4) & 1) * 16;         // bytes (+8 bf16)
    const int bRowN = (lane & 7);                      // + wn*32 + ni*8
    const int kHalfB = ((lane >> 3) & 1) * 16;

    // 3-stage pipeline: loads run 2 stages ahead of compute.
    load_stage(sb, 0, 0, m0, n0, tid);
    cp_commit();
    load_stage(sb, 1, 1, m0, n0, tid);
    cp_commit();

    for (int kc = 0; kc < NKC; kc++) {
        if (kc + 2 < NKC) {
            load_stage(sb, (kc + 2) % NSTAGE, kc + 2, m0, n0, tid);
            cp_commit();
            cp_wait<2>();                 // stage kc complete; kc+1,kc+2 may pend
        } else if (kc + 1 < NKC) {
            cp_wait<1>();                 // stage kc complete; kc+1 may pend
        } else {
            cp_wait<0>();
        }
        __syncthreads();

        const uint32_t st = sb + (kc % NSTAGE) * STAGE_BYTES;
#pragma unroll
        for (int ks = 0; ks < 4; ks++) {
            const uint32_t colA = (uint32_t)((ks * 32 + kHalfA) ^ l7x16);
            const uint32_t colB = (uint32_t)((ks * 32 + kHalfB) ^ l7x16);
            uint32_t ahi[4][4], alo[4][4], bhi[4][2], blo[4][2];
#pragma unroll
            for (int mi = 0; mi < 4; mi++) {
                const uint32_t ra = (uint32_t)((aRow + mi * 16) * 128) + colA;
                ldm_x4(ahi[mi], st + OFF_AHI + ra);
                ldm_x4(alo[mi], st + OFF_ALO + ra);
            }
#pragma unroll
            for (int ni = 0; ni < 4; ni++) {
                const uint32_t rb = (uint32_t)((wn * 32 + ni * 8 + bRowN) * 128) + colB;
                ldm_x2(bhi[ni], st + OFF_BHI + rb);
                ldm_x2(blo[ni], st + OFF_BLO + rb);
            }
#pragma unroll
            for (int mi = 0; mi < 4; mi++)
#pragma unroll
                for (int ni = 0; ni < 4; ni++) {
                    mma16816(d[mi][ni], ahi[mi], bhi[ni]);
                    mma16816(d[mi][ni], ahi[mi], blo[ni]);
                    mma16816(d[mi][ni], alo[mi], bhi[ni]);
                }
        }
        __syncthreads();   // release buffer kc%NSTAGE before load kc+3 overwrites it
    }

    // ---- epilogue: stage D tile in smem, coalesced V store + chunk sums ----
    {
        const int g = lane >> 2, tig = lane & 3;
        float* vs = (float*)dynsmem;   // reuse stage buffers: 128 x VS_STRIDE f32
#pragma unroll
        for (int mi = 0; mi < 4; mi++)
#pragma unroll
            for (int ni = 0; ni < 4; ni++) {
                const int r0 = wm * 64 + mi * 16 + g;
                const int c  = wn * 32 + ni * 8 + 2 * tig;
                *(float2*)&vs[(size_t)r0 * VS_STRIDE + c] =
                    make_float2(d[mi][ni][0], d[mi][ni][1]);
                *(float2*)&vs[(size_t)(r0 + 8) * VS_STRIDE + c] =
                    make_float2(d[mi][ni][2], d[mi][ni][3]);
            }
    }
    __syncthreads();

    // writeout: warp w -> rows w*16..w*16+15 (== one 16-row chunk); lane -> 4 cols
    {
        float* vs = (float*)dynsmem;
        float* part = (float*)(dynsmem + OFF_PART);  // [8][128]: chunk sums
        float4 sum = make_float4(0.f, 0.f, 0.f, 0.f);
#pragma unroll
        for (int i = 0; i < 16; i++) {
            const int r = wid * 16 + i;
            float4 v = *(float4*)&vs[(size_t)r * VS_STRIDE + lane * 4];
            sum.x += v.x; sum.y += v.y; sum.z += v.z; sum.w += v.w;
            *(float4*)&g_V[(size_t)(m0 + r) * NTOT + n0 + lane * 4] = v;
        }
        *(float4*)&part[wid * 128 + lane * 4] = sum;
    }
    __syncthreads();

    // chunk sums -> g_S [b][d][c]; chunk c (16 rows) == warp c of this tile
    {
        const float* part = (const float*)(dynsmem + OFF_PART);
        const int b = m0 >> 13;                // /8192
        const int cBase = (m0 & 8191) >> 4;    // /16
#pragma unroll
        for (int it = 0; it < 4; it++) {
            const int idx = tid + it * 256;    // 0..1023
            const int c = idx >> 7, col = idx & 127;
            g_S[((size_t)(b * NTOT + n0 + col)) * NCHK + cBase + c] = part[c * 128 + col];
        }
    }
}

// ================= exclusive prefix over chunk sums (per b,d) =================
__global__ __launch_bounds__(512) void prefix_kernel() {
    __shared__ float wsum[16];
    const size_t base = (size_t)blockIdx.x * NCHK;   // blockIdx.x = b*512 + d
    const int tid = threadIdx.x, lane = tid & 31, wid = tid >> 5;
    const float v = g_S[base + tid];
    float inc = v;
#pragma unroll
    for (int o = 1; o < 32; o <<= 1) {
        float t = __shfl_up_sync(0xffffffffu, inc, o);
        if (lane >= o) inc += t;
    }
    if (lane == 31) wsum[wid] = inc;
    __syncthreads();
    if (tid == 0) {
        float run = 0.f;
#pragma unroll
        for (int w = 0; w < 16; w++) { float t = wsum[w]; wsum[w] = run; run += t; }
    }
    __syncthreads();
    g_S[base + tid] = inc - v + wsum[wid];   // exclusive prefix
}

// ================= scan: running mean over 16-row chunks =================
__global__ __launch_bounds__(128) void scan_kernel(float* __restrict__ out) {
    const int c = blockIdx.x;
    const int b = blockIdx.y;
    const int d4 = threadIdx.x;                     // cols [4*d4, 4*d4+4)
    float4 run;
    run.x = g_S[((size_t)(b * NTOT + d4 * 4 + 0)) * NCHK + c];
    run.y = g_S[((size_t)(b * NTOT + d4 * 4 + 1)) * NCHK + c];
    run.z = g_S[((size_t)(b * NTOT + d4 * 4 + 2)) * NCHK + c];
    run.w = g_S[((size_t)(b * NTOT + d4 * 4 + 3)) * NCHK + c];
    const int l0 = c * CHUNK;
    const size_t base = ((size_t)b * LSEQ + l0) * NTOT + d4 * 4;
#pragma unroll 8
    for (int i = 0; i < CHUNK; i++) {
        float4 v = *(const float4*)&g_V[base + (size_t)i * NTOT];
        run.x += v.x; run.y += v.y; run.z += v.z; run.w += v.w;
        const float inv = 1.0f / (float)(l0 + i + 1);
        *(float4*)&out[base + (size_t)i * NTOT] =
            make_float4(run.x * inv, run.y * inv, run.z * inv, run.w * inv);
    }
}

// ================= launch =================
extern "C" void kernel_launch(void* const* d_in, const int* in_sizes, int n_in,
                              void* d_out, int out_size) {
    const float* x = (const float*)d_in[0];
    const float* W = (const float*)d_in[1];
    float* out = (float*)d_out;

    convert_kernel<<<2048, 256>>>(x, W);

    cudaFuncSetAttribute(gemm_kernel, cudaFuncAttributeMaxDynamicSharedMemorySize, SMEM_DYN);
    gemm_kernel<<<dim3(NTOT / BN, M_TOT / BM), 256, SMEM_DYN>>>();  // (4, 256)

    prefix_kernel<<<4 * NTOT, 512>>>();                              // 2048 blocks
    scan_kernel<<<dim3(NCHK, 4), 128>>>(out);
}